// round 5
// baseline (speedup 1.0000x reference)
#include <cuda_runtime.h>
#include <cstdint>
#include <math.h>

#define NB   8
#define LATD 128
#define HD   1024
#define KD   294
#define ND   100000
#define ED   1600000

// ---------------- scratch (device globals; no allocation allowed) ----------
__device__ __align__(16) float g_hT0[HD * NB];
__device__ __align__(16) float g_hT1[HD * NB];
__device__ __align__(16) float g_preT[HD * NB];
__device__ __align__(16) float g_cpre[3 * KD * NB];
__device__ __align__(16) float g_cbuf[KD * 24];          // [k][j], j = b*3+axis
__device__ __align__(16) float g_f[(size_t)ND * 24];     // [n][b*3+axis]
__device__ __align__(16) float g_agg[(size_t)ND * 24];
__device__ __align__(16) float g_sinv[ND];               // deg, then TAU/max(deg,1e-6)
__device__ float g_regsum;
__device__ int   g_is64;                                 // 1 if edge_index is int64

// ---------------- edge_index dtype detection --------------------------------
// int64 little-endian with values < 2^31 => every odd int32 word is 0.
// int32 random node ids => odd words are ordinary ids (P(all zero) ~ 0).
__global__ void k_detect(const int* __restrict__ ei32) {
    __shared__ int any_nonzero;
    int t = threadIdx.x;
    if (t == 0) any_nonzero = 0;
    __syncthreads();
    // sample 256 odd positions spread across the buffer's first row
    int v = ei32[2 * (t * 64) + 1];
    if (v != 0) atomicOr(&any_nonzero, 1);
    __syncthreads();
    if (t == 0) g_is64 = (any_nonzero == 0) ? 1 : 0;
}

__device__ __forceinline__ int load_ei(const int* __restrict__ ei32, size_t pos) {
    return g_is64 ? ei32[2 * pos] : ei32[pos];
}

// ---------------- layer 0: hT0[j][b] = relu(latent @ W0 + b0) --------------
__global__ void k_mlp0(const float* __restrict__ latent,
                       const float* __restrict__ W0,
                       const float* __restrict__ b0) {
    __shared__ __align__(16) float slat[LATD * NB];   // [i][b]
    int tid = threadIdx.x;
    for (int idx = tid; idx < LATD * NB; idx += 128) {
        int i = idx & (LATD - 1);
        int b = idx >> 7;
        slat[i * NB + b] = latent[b * LATD + i];
    }
    __syncthreads();
    int j = blockIdx.x * 128 + tid;
    float acc[NB];
#pragma unroll
    for (int b = 0; b < NB; b++) acc[b] = 0.f;
    const float* Wp = W0 + j;
#pragma unroll 4
    for (int i = 0; i < LATD; i++) {
        float w = Wp[i * HD];
        const float4* h4 = (const float4*)&slat[i * NB];
        float4 a = h4[0], c = h4[1];
        acc[0] += a.x * w; acc[1] += a.y * w; acc[2] += a.z * w; acc[3] += a.w * w;
        acc[4] += c.x * w; acc[5] += c.y * w; acc[6] += c.z * w; acc[7] += c.w * w;
    }
    float bb = b0[j];
#pragma unroll
    for (int b = 0; b < NB; b++) g_hT0[j * NB + b] = fmaxf(acc[b] + bb, 0.f);
}

// -------- residual layer, split-K partial sums into g_preT ------------------
__global__ void k_layer_splitK(const float* __restrict__ hT,
                               const float* __restrict__ W) {
    __shared__ __align__(16) float sh[128 * NB];      // [ii][b]
    int tid = threadIdx.x;
    int i0 = blockIdx.y * 128;
    const float4* src = (const float4*)(hT + (size_t)i0 * NB);
    float4* d4 = (float4*)sh;
    for (int t = tid; t < 256; t += 128) d4[t] = src[t];
    __syncthreads();
    int j = blockIdx.x * 128 + tid;
    float acc[NB];
#pragma unroll
    for (int b = 0; b < NB; b++) acc[b] = 0.f;
    const float* Wp = W + (size_t)i0 * HD + j;
#pragma unroll 4
    for (int ii = 0; ii < 128; ii++) {
        float w = Wp[(size_t)ii * HD];
        const float4* h4 = (const float4*)&sh[ii * NB];
        float4 a = h4[0], c = h4[1];
        acc[0] += a.x * w; acc[1] += a.y * w; acc[2] += a.z * w; acc[3] += a.w * w;
        acc[4] += c.x * w; acc[5] += c.y * w; acc[6] += c.z * w; acc[7] += c.w * w;
    }
#pragma unroll
    for (int b = 0; b < NB; b++) atomicAdd(&g_preT[j * NB + b], acc[b]);
}

__global__ void k_layer_epi(const float* __restrict__ hT_in,
                            float* __restrict__ hT_out,
                            const float* __restrict__ bias) {
    int j = blockIdx.x * 128 + threadIdx.x;
    float bb = bias[j];
#pragma unroll
    for (int b = 0; b < NB; b++) {
        float v = hT_in[j * NB + b] + g_preT[j * NB + b] + bb;
        hT_out[j * NB + b] = fmaxf(v, 0.f);
    }
}

// -------- coefficient heads, split-K ----------------------------------------
__global__ void k_coeff_splitK(const float* __restrict__ hT,
                               const float* __restrict__ Wx,
                               const float* __restrict__ Wy,
                               const float* __restrict__ Wz) {
    __shared__ __align__(16) float sh[128 * NB];
    int tid = threadIdx.x;
    int i0 = blockIdx.y * 128;
    const float4* src = (const float4*)(hT + (size_t)i0 * NB);
    float4* d4 = (float4*)sh;
    if (tid < 256) d4[tid] = src[tid];
    __syncthreads();
    int k = tid;
    if (k >= KD) return;
    int axis = blockIdx.x;
    const float* W = (axis == 0) ? Wx : ((axis == 1) ? Wy : Wz);
    const float* Wp = W + (size_t)i0 * KD + k;
    float acc[NB];
#pragma unroll
    for (int b = 0; b < NB; b++) acc[b] = 0.f;
#pragma unroll 4
    for (int ii = 0; ii < 128; ii++) {
        float w = Wp[(size_t)ii * KD];
        const float4* h4 = (const float4*)&sh[ii * NB];
        float4 a = h4[0], c = h4[1];
        acc[0] += a.x * w; acc[1] += a.y * w; acc[2] += a.z * w; acc[3] += a.w * w;
        acc[4] += c.x * w; acc[5] += c.y * w; acc[6] += c.z * w; acc[7] += c.w * w;
    }
    float* dst = &g_cpre[((size_t)axis * KD + k) * NB];
#pragma unroll
    for (int b = 0; b < NB; b++) atomicAdd(&dst[b], acc[b]);
}

// writes c scaled by 0.5*XSIZE=64 into g_cbuf (GEMM consumes it directly);
// reg uses the UNscaled values.
__global__ void k_coeff_epi(const float* __restrict__ bx,
                            const float* __restrict__ by,
                            const float* __restrict__ bz) {
    int k = blockIdx.x * blockDim.x + threadIdx.x;
    if (k >= KD) return;
    float ss = 0.f;
#pragma unroll
    for (int axis = 0; axis < 3; axis++) {
        const float* bias = (axis == 0) ? bx : ((axis == 1) ? by : bz);
        float bb = bias[k];
#pragma unroll
        for (int b = 0; b < NB; b++) {
            float v = g_cpre[((size_t)axis * KD + k) * NB + b] + bb;
            g_cbuf[k * 24 + b * 3 + axis] = 64.f * v;
            ss += v * v;
        }
    }
    atomicAdd(&g_regsum, ss);
}

// -------- big GEMM: f[n][j] = sum_k cbuf[k][j] * Z[k][n] --------------------
__global__ __launch_bounds__(64) void k_gemm(const float* __restrict__ Z) {
    __shared__ __align__(16) float4 cs[KD * 6];       // row k = 6 float4 = 24 c values
    int tid = threadIdx.x;
    const float4* cb4 = (const float4*)g_cbuf;
    for (int t = tid; t < KD * 6; t += 64) cs[t] = cb4[t];
    __syncthreads();
    int n = blockIdx.x * 256 + tid * 4;
    if (n >= ND) return;
    float acc[96];                                    // acc[j*4 + comp]
#pragma unroll
    for (int t = 0; t < 96; t++) acc[t] = 0.f;
    const float4* Zp = (const float4*)Z + (n >> 2);
    for (int k = 0; k < KD; k++) {
        float4 z = Zp[(size_t)k * (ND / 4)];
        float zz[4] = {z.x, z.y, z.z, z.w};
        const float4* cr = &cs[k * 6];
#pragma unroll
        for (int q = 0; q < 6; q++) {
            float4 c = cr[q];
            float cc[4] = {c.x, c.y, c.z, c.w};
#pragma unroll
            for (int t = 0; t < 4; t++)
#pragma unroll
                for (int comp = 0; comp < 4; comp++)
                    acc[(q * 4 + t) * 4 + comp] += cc[t] * zz[comp];
        }
    }
#pragma unroll
    for (int comp = 0; comp < 4; comp++) {
        float4* out = (float4*)(g_f + (size_t)(n + comp) * 24);
#pragma unroll
        for (int q = 0; q < 6; q++) {
            out[q] = make_float4(acc[(q * 4 + 0) * 4 + comp],
                                 acc[(q * 4 + 1) * 4 + comp],
                                 acc[(q * 4 + 2) * 4 + comp],
                                 acc[(q * 4 + 3) * 4 + comp]);
        }
    }
}

// -------- diffusion ---------------------------------------------------------
__global__ void k_deg(const int* __restrict__ ei32,
                      const float* __restrict__ ew) {
    int e = blockIdx.x * 256 + threadIdx.x;
    if (e >= ED) return;
    int d = load_ei(ei32, (size_t)ED + e);
    if ((unsigned)d >= ND) return;
    atomicAdd(&g_sinv[d], ew[e]);
}

__global__ void k_sinv() {
    int n = blockIdx.x * 256 + threadIdx.x;
    if (n >= ND) return;
    g_sinv[n] = 0.5f / fmaxf(g_sinv[n], 1e-6f);
}

__global__ void k_scatter(const int* __restrict__ ei32,
                          const float* __restrict__ ew) {
    int e = blockIdx.x * 256 + threadIdx.x;
    if (e >= ED) return;
    int s = load_ei(ei32, (size_t)e);
    int d = load_ei(ei32, (size_t)ED + e);
    if ((unsigned)s >= ND || (unsigned)d >= ND) return;
    float w = ew[e];
    const float4* fs = (const float4*)(g_f + (size_t)s * 24);
    float4* ag = (float4*)(g_agg + (size_t)d * 24);
#pragma unroll
    for (int q = 0; q < 6; q++) {
        float4 m = fs[q];
        atomicAdd(&ag[q], make_float4(m.x * w, m.y * w, m.z * w, m.w * w));
    }
}

__global__ void k_combine() {
    int t = blockIdx.x * 256 + threadIdx.x;
    if (t >= ND * 6) return;
    float4 f = ((const float4*)g_f)[t];
    float4 a = ((const float4*)g_agg)[t];
    float s = g_sinv[t / 6];
    ((float4*)g_f)[t] = make_float4(0.5f * f.x + a.x * s, 0.5f * f.y + a.y * s,
                                    0.5f * f.z + a.z * s, 0.5f * f.w + a.w * s);
}

// -------- output transpose [n][b][axis] -> [b][n][axis] ---------------------
__global__ void k_output(float* __restrict__ out) {
    int g = blockIdx.x * 256 + threadIdx.x;
    if (g >= NB * ND) return;
    int b = g / ND;
    int n = g - b * ND;
    const float* fp = g_f + (size_t)n * 24 + b * 3;
    float* op = out + (size_t)b * (ND * 3) + (size_t)n * 3;
    op[0] = fp[0]; op[1] = fp[1]; op[2] = fp[2];
}

__global__ void k_reg(float* __restrict__ out, int do_write) {
    if (do_write) out[(size_t)NB * ND * 3] = 1e-4f * sqrtf(g_regsum);
}

// ---------------------------------------------------------------------------
extern "C" void kernel_launch(void* const* d_in, const int* in_sizes, int n_in,
                              void* d_out, int out_size) {
    const float* latent = (const float*)d_in[0];
    const float* W0 = (const float*)d_in[1];
    const float* b0 = (const float*)d_in[2];
    const float* W1 = (const float*)d_in[3];
    const float* b1 = (const float*)d_in[4];
    const float* W2 = (const float*)d_in[5];
    const float* b2 = (const float*)d_in[6];
    const float* W3 = (const float*)d_in[7];
    const float* b3 = (const float*)d_in[8];
    const float* Wx = (const float*)d_in[9];
    const float* bx = (const float*)d_in[10];
    const float* Wy = (const float*)d_in[11];
    const float* by = (const float*)d_in[12];
    const float* Wz = (const float*)d_in[13];
    const float* bz = (const float*)d_in[14];
    const float* Z  = (const float*)d_in[15];
    const float* ew = (const float*)d_in[16];
    const int*   ei = (const int*)d_in[17];   // int32 OR int64 (auto-detected)
    float* out = (float*)d_out;

    void *p_pre, *p_cpre, *p_sinv, *p_agg, *p_reg, *p_h0, *p_h1;
    cudaGetSymbolAddress(&p_h0, g_hT0);
    cudaGetSymbolAddress(&p_h1, g_hT1);
    cudaGetSymbolAddress(&p_pre, g_preT);
    cudaGetSymbolAddress(&p_cpre, g_cpre);
    cudaGetSymbolAddress(&p_sinv, g_sinv);
    cudaGetSymbolAddress(&p_agg, g_agg);
    cudaGetSymbolAddress(&p_reg, g_regsum);

    cudaMemsetAsync(p_sinv, 0, (size_t)ND * sizeof(float));
    cudaMemsetAsync(p_reg, 0, sizeof(float));

    k_detect<<<1, 256>>>(ei);

    // MLP decode
    k_mlp0<<<8, 128>>>(latent, W0, b0);
    const float* Ws[3] = {W1, W2, W3};
    const float* bs[3] = {b1, b2, b3};
    float* hin = (float*)p_h0;
    float* hout = (float*)p_h1;
    for (int l = 0; l < 3; l++) {
        cudaMemsetAsync(p_pre, 0, (size_t)HD * NB * sizeof(float));
        k_layer_splitK<<<dim3(8, 8), 128>>>(hin, Ws[l]);
        k_layer_epi<<<8, 128>>>(hin, hout, bs[l]);
        float* tmp = hin; hin = hout; hout = tmp;
    }
    cudaMemsetAsync(p_cpre, 0, (size_t)3 * KD * NB * sizeof(float));
    k_coeff_splitK<<<dim3(3, 8), 320>>>(hin, Wx, Wy, Wz);
    k_coeff_epi<<<3, 128>>>(bx, by, bz);

    // dense projection onto basis Z
    k_gemm<<<(ND + 255) / 256, 64>>>(Z);

    // graph diffusion
    k_deg<<<(ED + 255) / 256, 256>>>(ei, ew);
    k_sinv<<<(ND + 255) / 256, 256>>>();
    for (int s = 0; s < 3; s++) {
        cudaMemsetAsync(p_agg, 0, (size_t)ND * 24 * sizeof(float));
        k_scatter<<<(ED + 255) / 256, 256>>>(ei, ew);
        k_combine<<<(ND * 6 + 255) / 256, 256>>>();
    }

    // outputs
    k_output<<<(NB * ND + 255) / 256, 256>>>(out);
    k_reg<<<1, 1>>>(out, (out_size > NB * ND * 3) ? 1 : 0);
}